// round 7
// baseline (speedup 1.0000x reference)
#include <cuda_runtime.h>
#include <math.h>

// ---------------------------------------------------------------------------
// Problem constants
//   L=32, M=2L-1=63  -> SL = L*M = 2016 spatial samples
//   nlm = L*L = 1024 compact spectral coefficients (idx scatter positions)
//   B=32, IN_C=OUT_C=64, H=8, D=8  -> NR = B*64 = 2048 "attention rows"
//
// I/O convention (established R5+R6): harness converts complex64 arrays with
// astype(float32) semantics -> REAL PART ONLY, element count preserved.
//   - Ymat  input: SL*NLM floats = Re(Ymat[s,k]), row-major [s,k]
//   - Ypinv input: NLM*SL floats = Re(Ypinv[k,s]), row-major [k,s]
//   - output: NOUT floats = Re(out[b,o,l,m])
// Imag parts are reconstructed exactly from the separable phi structure:
//   Ymat[tM+p, k(l,m)]  = C[t,k] e^{+i m phi_p},  C = Re at p=0
//   Ypinv[k, tM+p]      = D[k,t] e^{-i m phi_p},  D = Re at p=0
// ---------------------------------------------------------------------------
#define SL    2016
#define NPHI  63
#define NLM   1024
#define NB    32
#define NCH   64
#define NR    2048     // NB * NCH
#define NKR   512      // H*D*D rows per q/k/v kernel
#define NK3   1536     // 3 * NKR
#define NKO   4096     // OUT_C * IN_C
#define NOUT  (NB * NCH * SL)   // 4,128,768 output elements (floats)

// ---------------------------------------------------------------------------
// Static device scratch (no allocation allowed)
// ---------------------------------------------------------------------------
__device__ float  g_Ypv [2 * NLM * SL];   // Ypinv de-interleaved: row 2k = Re, 2k+1 = Im  [2048, 2016]
__device__ float  g_Yv  [SL * 2 * NLM];   // Ymat (Re, -Im) interleaved along K            [2016, 2048]
__device__ float  g_kcat[NK3 * SL];       // concat of k_q|k_k|k_v spatial                 [1536, 2016]
__device__ float  g_ko  [NKO * SL];       // copy of k_o spatial                           [4096, 2016]
__device__ float  g_fc  [NR * NLM];       // gathered f at idx positions                   [2048, 1024]
__device__ float  g_kqkv[NK3 * 2 * NLM];  // spectral q|k|v kernels, complex interleaved   [1536, 1024]c
__device__ float  g_koc [NKO * 2 * NLM];  // spectral output kernel, complex interleaved   [4096, 1024]c
__device__ float2 g_kot [NLM * NKO];      // transposed: [k][o*64+c]
__device__ float2 g_G   [NR * NLM];       // FQ * conj(FK)
__device__ float2 g_FV  [NR * NLM];
__device__ float  g_Asp [NR * SL];        // spatial attention logits -> softmax in place
__device__ float  g_FA  [NR * 2 * NLM];   // fsht(softmax), complex interleaved
__device__ float2 g_fot [NLM * NR];       // (FV*FA) transposed: [k][b*64+ch]

// Device pointer table: avoids host-side symbol-address lookup (R1-R4 crash).
__device__ float* g_ptab[16];

__global__ void init_ptab() {
    g_ptab[0] = g_Ypv;
    g_ptab[1] = g_Yv;
    g_ptab[2] = g_kcat;
    g_ptab[3] = g_kqkv;
    g_ptab[4] = g_ko;
    g_ptab[5] = g_koc;
    g_ptab[6] = reinterpret_cast<float*>(g_G);
    g_ptab[7] = g_Asp;
    g_ptab[8] = g_FA;
}

// ---------------------------------------------------------------------------
// Helpers
// ---------------------------------------------------------------------------
__device__ __forceinline__ int iclamp(int i, int n) {
    return (i < 0) ? 0 : ((i >= n) ? n - 1 : i);
}

__device__ __forceinline__ int isqrt_dev(int k) {
    int l = (int)sqrtf((float)k);
    while ((l + 1) * (l + 1) <= k) ++l;
    while (l * l > k) --l;
    return l;
}

// sin(2*pi*(m*p mod 63)/63) with exact integer reduction
__device__ __forceinline__ float sin_mphi(int m, int p) {
    int q = (m * p) % NPHI;
    if (q < 0) q += NPHI;
    return sinf(6.2831853071795864769f * (float)q / (float)NPHI);
}

// ---------------------------------------------------------------------------
// Prep kernels. mode == 0: input is real-part-only (astype semantics), imag
// reconstructed. mode == 1: input is interleaved re/im floats (fallback).
// ---------------------------------------------------------------------------
__global__ void prep_Ypv(const float* __restrict__ buf, int mode) {
    int i = blockIdx.x * blockDim.x + threadIdx.x;
    if (i >= NLM * SL) return;
    int k = i / SL, s = i - k * SL;
    float re, im;
    if (mode == 0) {
        int t = s / NPHI, p = s - t * NPHI;
        int l = isqrt_dev(k);
        int m = k - l * l - l;
        re = buf[i];
        float base = buf[k * SL + t * NPHI];   // p = 0
        im = -base * sin_mphi(m, p);           // Ypinv ~ e^{-i m phi}
    } else {
        re = buf[2 * i];
        im = buf[2 * i + 1];
    }
    g_Ypv[(size_t)(2 * k) * SL + s]     = re;
    g_Ypv[(size_t)(2 * k + 1) * SL + s] = im;
}

__global__ void prep_Yv(const float* __restrict__ buf, int mode) {
    int i = blockIdx.x * blockDim.x + threadIdx.x;
    if (i >= SL * NLM) return;
    int s = i / NLM, k = i - s * NLM;
    float re, im;
    if (mode == 0) {
        int t = s / NPHI, p = s - t * NPHI;
        int l = isqrt_dev(k);
        int m = k - l * l - l;
        re = buf[i];
        float base = buf[(size_t)(t * NPHI) * NLM + k];  // p = 0
        im = base * sin_mphi(m, p);            // Ymat ~ e^{+i m phi}
    } else {
        re = buf[2 * i];
        im = buf[2 * i + 1];
    }
    g_Yv[(size_t)2 * i]     = re;
    g_Yv[(size_t)2 * i + 1] = -im;             // (Re, -Im) for Re-part GEMM
}

__global__ void concat_k(const float* __restrict__ kq, int nq,
                         const float* __restrict__ kk, int nk,
                         const float* __restrict__ kv, int nv) {
    int i = blockIdx.x * blockDim.x + threadIdx.x;
    if (i >= NKR * SL) return;
    g_kcat[i]                        = kq[iclamp(i, nq)];
    g_kcat[i + (size_t)NKR * SL]     = kk[iclamp(i, nk)];
    g_kcat[i + (size_t)2 * NKR * SL] = kv[iclamp(i, nv)];
}

__global__ void copy_ko(const float* __restrict__ ko, int n) {
    int i = blockIdx.x * blockDim.x + threadIdx.x;
    if (i >= NKO * SL) return;
    g_ko[i] = ko[iclamp(i, n)];
}

__global__ void gather_fc(const float* __restrict__ f_in, int nf,
                          const int* __restrict__ idx, int ni) {
    int i = blockIdx.x * blockDim.x + threadIdx.x;
    if (i >= NR * NLM) return;
    int r = i >> 10, k = i & (NLM - 1);
    int s = idx[iclamp(k, ni)];
    s = iclamp(s, SL);
    g_fc[i] = f_in[iclamp(r * SL + s, nf)];
}

// ---------------------------------------------------------------------------
// NT SGEMM: C[m,n] = sum_k A[m*lda+k] * B[n*ldb+k]
// 128x128 tile, BK=16, 256 threads, 8x8 per thread, double-buffered smem.
// ---------------------------------------------------------------------------
#define LOAD_TILE(KT)                                                                     \
    {                                                                                     \
        int ra0 = bm + lrow0, ra1 = bm + lrow0 + 64;                                      \
        pa0 = z4; pa1 = z4; pb0 = z4; pb1 = z4;                                           \
        if (ra0 < M) pa0 = *reinterpret_cast<const float4*>(A + (size_t)ra0 * lda + (KT) + lcol); \
        if (ra1 < M) pa1 = *reinterpret_cast<const float4*>(A + (size_t)ra1 * lda + (KT) + lcol); \
        int rb0 = bn + lrow0, rb1 = bn + lrow0 + 64;                                      \
        if (rb0 < N) pb0 = *reinterpret_cast<const float4*>(B + (size_t)rb0 * ldb + (KT) + lcol); \
        if (rb1 < N) pb1 = *reinterpret_cast<const float4*>(B + (size_t)rb1 * ldb + (KT) + lcol); \
    }

#define STORE_TILE(BUF)                                                                   \
    {                                                                                     \
        As[BUF][lcol + 0][lrow0] = pa0.x; As[BUF][lcol + 1][lrow0] = pa0.y;               \
        As[BUF][lcol + 2][lrow0] = pa0.z; As[BUF][lcol + 3][lrow0] = pa0.w;               \
        As[BUF][lcol + 0][lrow0 + 64] = pa1.x; As[BUF][lcol + 1][lrow0 + 64] = pa1.y;     \
        As[BUF][lcol + 2][lrow0 + 64] = pa1.z; As[BUF][lcol + 3][lrow0 + 64] = pa1.w;     \
        Bs[BUF][lcol + 0][lrow0] = pb0.x; Bs[BUF][lcol + 1][lrow0] = pb0.y;               \
        Bs[BUF][lcol + 2][lrow0] = pb0.z; Bs[BUF][lcol + 3][lrow0] = pb0.w;               \
        Bs[BUF][lcol + 0][lrow0 + 64] = pb1.x; Bs[BUF][lcol + 1][lrow0 + 64] = pb1.y;     \
        Bs[BUF][lcol + 2][lrow0 + 64] = pb1.z; Bs[BUF][lcol + 3][lrow0 + 64] = pb1.w;     \
    }

__global__ __launch_bounds__(256) void sgemm_nt(
    int ia, int ib, int ic,
    int M, int N, int K, int lda, int ldb, int ldc)
{
    const float* __restrict__ A = g_ptab[ia];
    const float* __restrict__ B = g_ptab[ib];
    float* __restrict__ C = g_ptab[ic];

    __shared__ __align__(16) float As[2][16][128];
    __shared__ __align__(16) float Bs[2][16][128];
    const int tid = threadIdx.x;
    const int tx = tid & 15;
    const int ty = tid >> 4;
    const int bm = blockIdx.y * 128;
    const int bn = blockIdx.x * 128;
    const int lrow0 = tid >> 2;
    const int lcol  = (tid & 3) * 4;

    float acc[8][8];
#pragma unroll
    for (int i = 0; i < 8; i++)
#pragma unroll
        for (int j = 0; j < 8; j++) acc[i][j] = 0.f;

    float4 pa0, pa1, pb0, pb1;
    const float4 z4 = make_float4(0.f, 0.f, 0.f, 0.f);

    LOAD_TILE(0)
    STORE_TILE(0)
    __syncthreads();

    const int nt = K / 16;
    for (int t = 0; t < nt; ++t) {
        const int cur = t & 1;
        if (t + 1 < nt) LOAD_TILE((t + 1) * 16)
#pragma unroll
        for (int kk = 0; kk < 16; ++kk) {
            float4 a0 = *reinterpret_cast<const float4*>(&As[cur][kk][ty * 8]);
            float4 a1 = *reinterpret_cast<const float4*>(&As[cur][kk][ty * 8 + 4]);
            float4 b0 = *reinterpret_cast<const float4*>(&Bs[cur][kk][tx * 8]);
            float4 b1 = *reinterpret_cast<const float4*>(&Bs[cur][kk][tx * 8 + 4]);
            float ra[8] = {a0.x, a0.y, a0.z, a0.w, a1.x, a1.y, a1.z, a1.w};
            float rb[8] = {b0.x, b0.y, b0.z, b0.w, b1.x, b1.y, b1.z, b1.w};
#pragma unroll
            for (int i = 0; i < 8; ++i)
#pragma unroll
                for (int j = 0; j < 8; ++j) acc[i][j] += ra[i] * rb[j];
        }
        if (t + 1 < nt) {
            const int nxt = cur ^ 1;
            STORE_TILE(nxt)
            __syncthreads();
        }
    }

#pragma unroll
    for (int i = 0; i < 8; ++i) {
        int row = bm + ty * 8 + i;
        if (row >= M) continue;
#pragma unroll
        for (int j = 0; j < 8; ++j) {
            int col = bn + tx * 8 + j;
            if (col < N) C[(size_t)row * ldc + col] = acc[i][j];
        }
    }
}

// ---------------------------------------------------------------------------
// Complex transpose g_koc [NKO][NLM]c -> g_kot [NLM][NKO]c
// ---------------------------------------------------------------------------
__global__ void transpose_koc() {
    __shared__ __align__(16) float2 tile[32][33];
    int c0 = blockIdx.x * 32, r0 = blockIdx.y * 32;
    const float2* in = reinterpret_cast<const float2*>(g_koc);
#pragma unroll
    for (int j = 0; j < 4; ++j) {
        int r = r0 + threadIdx.y + j * 8;
        tile[threadIdx.y + j * 8][threadIdx.x] = in[(size_t)r * NLM + c0 + threadIdx.x];
    }
    __syncthreads();
#pragma unroll
    for (int j = 0; j < 4; ++j) {
        int c = c0 + threadIdx.y + j * 8;
        g_kot[(size_t)c * NKO + r0 + threadIdx.x] = tile[threadIdx.x][threadIdx.y + j * 8];
    }
}

// ---------------------------------------------------------------------------
// Fused head-mixing: FQ/FK/FV (D=8 contraction, f real) + G = FQ * conj(FK)
// ---------------------------------------------------------------------------
__global__ __launch_bounds__(256) void qkv_g() {
    int k = blockIdx.x * 256 + threadIdx.x;   // 0..1023
    int r = blockIdx.y;                       // 0..2047 : (b, h, d)
    int b = r >> 6, ch = r & 63, h = ch >> 3, d = ch & 7;
    const float2* kc = reinterpret_cast<const float2*>(g_kqkv);
    float qr = 0, qi = 0, kr = 0, ki = 0, vr = 0, vi = 0;
#pragma unroll
    for (int c = 0; c < 8; ++c) {
        float f = g_fc[(size_t)((b << 6) + (h << 3) + c) * NLM + k];
        int row = ((h << 3) + c) * 8 + d;
        float2 wq = kc[(size_t)row * NLM + k];
        float2 wk = kc[(size_t)(row + NKR) * NLM + k];
        float2 wv = kc[(size_t)(row + 2 * NKR) * NLM + k];
        qr += f * wq.x; qi += f * wq.y;
        kr += f * wk.x; ki += f * wk.y;
        vr += f * wv.x; vi += f * wv.y;
    }
    size_t o = (size_t)r * NLM + k;
    g_G[o]  = make_float2(qr * kr + qi * ki, qi * kr - qr * ki);
    g_FV[o] = make_float2(vr, vi);
}

// ---------------------------------------------------------------------------
// Row softmax over SL=2016 columns, in place on g_Asp
// ---------------------------------------------------------------------------
__global__ __launch_bounds__(256) void softmax_rows() {
    __shared__ float red[32];
    float* row = g_Asp + (size_t)blockIdx.x * SL;
    int tid = threadIdx.x;

    float m = -1e30f;
    for (int i = tid; i < SL; i += 256) m = fmaxf(m, row[i]);
#pragma unroll
    for (int o = 16; o; o >>= 1) m = fmaxf(m, __shfl_xor_sync(0xffffffffu, m, o));
    if ((tid & 31) == 0) red[tid >> 5] = m;
    __syncthreads();
    if (tid < 32) {
        float v = (tid < 8) ? red[tid] : -1e30f;
#pragma unroll
        for (int o = 4; o; o >>= 1) v = fmaxf(v, __shfl_xor_sync(0xffffffffu, v, o));
        if (tid == 0) red[0] = v;
    }
    __syncthreads();
    m = red[0];
    __syncthreads();

    float s = 0.f;
    for (int i = tid; i < SL; i += 256) {
        float e = expf(row[i] - m);
        row[i] = e;
        s += e;
    }
#pragma unroll
    for (int o = 16; o; o >>= 1) s += __shfl_xor_sync(0xffffffffu, s, o);
    if ((tid & 31) == 0) red[tid >> 5] = s;
    __syncthreads();
    if (tid < 32) {
        float v = (tid < 8) ? red[tid] : 0.f;
#pragma unroll
        for (int o = 4; o; o >>= 1) v += __shfl_xor_sync(0xffffffffu, v, o);
        if (tid == 0) red[0] = v;
    }
    __syncthreads();
    float inv = 1.0f / red[0];
    for (int i = tid; i < SL; i += 256) row[i] *= inv;
}

// ---------------------------------------------------------------------------
// f_out = FV * FA (complex), transposed into [k][r] layout
// ---------------------------------------------------------------------------
__global__ void fout_transpose() {
    __shared__ __align__(16) float2 tile[32][33];
    int k0 = blockIdx.x * 32, r0 = blockIdx.y * 32;
    const float2* FA2 = reinterpret_cast<const float2*>(g_FA);
#pragma unroll
    for (int j = 0; j < 4; ++j) {
        int r = r0 + threadIdx.y + j * 8;
        size_t p = (size_t)r * NLM + k0 + threadIdx.x;
        float2 v = g_FV[p];
        float2 a = FA2[p];
        tile[threadIdx.y + j * 8][threadIdx.x] =
            make_float2(v.x * a.x - v.y * a.y, v.x * a.y + v.y * a.x);
    }
    __syncthreads();
#pragma unroll
    for (int j = 0; j < 4; ++j) {
        int k = k0 + threadIdx.y + j * 8;
        g_fot[(size_t)k * NR + r0 + threadIdx.x] = tile[threadIdx.x][threadIdx.y + j * 8];
    }
}

// ---------------------------------------------------------------------------
// Output: d_out holds NOUT float32 = REAL PART of the complex result
// (astype semantics). interleaved==1 fallback kept for out_size >= 2*NOUT.
// ---------------------------------------------------------------------------
__global__ void zero_out_f(float* out, int n) {
    int i = blockIdx.x * blockDim.x + threadIdx.x;
    if (i < n) out[i] = 0.f;
}

__global__ __launch_bounds__(256) void out_scatter(const int* __restrict__ idx, int ni,
                                                   float* __restrict__ out, int interleaved) {
    __shared__ __align__(16) float2 Fsh[64 * 33];   // [c][b] with pad
    int k = blockIdx.x;
    for (int j = threadIdx.x; j < NR; j += 256) {
        float2 v = g_fot[(size_t)k * NR + j];
        int bb = j >> 6, cc = j & 63;
        Fsh[cc * 33 + bb] = v;
    }
    __syncthreads();
    int w = threadIdx.x >> 5;   // warp id -> base o
    int b = threadIdx.x & 31;
    const float2* W = g_kot + (size_t)k * NKO;
    float2 acc[8];
#pragma unroll
    for (int i = 0; i < 8; ++i) acc[i] = make_float2(0.f, 0.f);
#pragma unroll 4
    for (int c = 0; c < 64; ++c) {
        float2 F = Fsh[c * 33 + b];
#pragma unroll
        for (int i = 0; i < 8; ++i) {
            float2 ww = W[(w + i * 8) * 64 + c];
            acc[i].x += F.x * ww.x - F.y * ww.y;
            acc[i].y += F.x * ww.y + F.y * ww.x;
        }
    }
    int s = idx[iclamp(k, ni)];
    s = iclamp(s, SL);
#pragma unroll
    for (int i = 0; i < 8; ++i) {
        int o = w + i * 8;
        size_t e = (size_t)((b << 6) + o) * SL + s;   // element index < NOUT
        if (interleaved) {
            reinterpret_cast<float2*>(out)[e] = acc[i];
        } else {
            out[e] = acc[i].x;                        // real part only
        }
    }
}

// ---------------------------------------------------------------------------
// Launch
// ---------------------------------------------------------------------------
extern "C" void kernel_launch(void* const* d_in, const int* in_sizes, int n_in,
                              void* d_out, int out_size) {
    const float* f_in = (const float*)d_in[0];
    const float* kq   = (const float*)d_in[1];
    const float* kk   = (const float*)d_in[2];
    const float* kv   = (const float*)d_in[3];
    const float* ko   = (const float*)d_in[4];
    const float* Ym   = (const float*)d_in[5];
    const float* Yp   = (const float*)d_in[6];
    const int*   idx  = (const int*)d_in[7];

    // mode 0 = real-part-only buffer (expected); 1 = interleaved re/im floats
    const int ym_mode = (in_sizes[5] >= 2 * SL * NLM) ? 1 : 0;
    const int yp_mode = (in_sizes[6] >= 2 * SL * NLM) ? 1 : 0;
    const int idx_n   = in_sizes[7];

    float* out = (float*)d_out;
    const int interleaved = (out_size >= 2 * NOUT) ? 1 : 0;
    const int nzero = interleaved ? 2 * NOUT : NOUT;

    init_ptab<<<1, 1>>>();

    // prep
    prep_Ypv<<<(NLM * SL + 255) / 256, 256>>>(Yp, yp_mode);
    prep_Yv<<<(SL * NLM + 255) / 256, 256>>>(Ym, ym_mode);
    concat_k<<<(NKR * SL + 255) / 256, 256>>>(kq, in_sizes[1], kk, in_sizes[2], kv, in_sizes[3]);
    copy_ko<<<(NKO * SL + 255) / 256, 256>>>(ko, in_sizes[4]);
    gather_fc<<<(NR * NLM) / 256, 256>>>(f_in, in_sizes[0], idx, idx_n);

    // spectral kernel transforms (real x complex -> interleaved complex)
    sgemm_nt<<<dim3(16, 12), 256>>>(2, 0, 3, NK3, 2 * NLM, SL, SL, SL, 2 * NLM);
    sgemm_nt<<<dim3(16, 32), 256>>>(4, 0, 5, NKO, 2 * NLM, SL, SL, SL, 2 * NLM);
    transpose_koc<<<dim3(NLM / 32, NKO / 32), dim3(32, 8)>>>();

    // head mixing + G = FQ * conj(FK)
    qkv_g<<<dim3(NLM / 256, NR), 256>>>();

    // isht: A_sp = Re(G @ Ymat^T)  [2048, 2016]
    sgemm_nt<<<dim3(16, 16), 256>>>(6, 1, 7, NR, SL, 2 * NLM, 2 * NLM, 2 * NLM, SL);
    softmax_rows<<<NR, 256>>>();
    // fsht: FA = softmax(A) @ Ypinv^T  (complex interleaved)
    sgemm_nt<<<dim3(16, 16), 256>>>(7, 0, 8, NR, 2 * NLM, SL, SL, SL, 2 * NLM);

    // f_out = FV * FA, transposed to [k][r]
    fout_transpose<<<dim3(NLM / 32, NR / 32), dim3(32, 8)>>>();

    // final projection + scatter (real part into NOUT-float output)
    zero_out_f<<<(nzero + 255) / 256, 256>>>(out, nzero);
    out_scatter<<<NLM, 256>>>(idx, idx_n, out, interleaved);
}

// round 8
// speedup vs baseline: 4.6598x; 4.6598x over previous
#include <cuda_runtime.h>
#include <math.h>

// ---------------------------------------------------------------------------
// Constants: L=32, M=63, SL=2016, nlm=1024, B=32, C=64, H=8, D=8
// Separable SHT (validated R7, rel_err 1.8e-6):
//   Ypinv[k, t*63+p] = D[k,t] e^{-i m_k phi_p},  D = Re(Ypinv) at p=0
//   Ymat [t*63+p, k] = C[t,k] e^{+i m_k phi_p},  C = Re(Ymat)  at p=0
// So each transform = 63-pt phi-DFT + small Legendre contraction.
// I/O: complex arrays arrive/depart as REAL PART float32 (astype semantics).
// ---------------------------------------------------------------------------
#define SL    2016
#define NPHI  63
#define NLM   1024
#define NB    32
#define NCH   64
#define NR    2048
#define NKR   512
#define NK3   1536
#define NKO   4096
#define NOUT  (NB * NCH * SL)
#define ZROWS 245760           // (1536+4096+2048)*32 DFT rows

// ---------------------------------------------------------------------------
// Static device scratch
// ---------------------------------------------------------------------------
__device__ float  g_D [32 * NLM];          // D[t][k]   (Legendre, forward)
__device__ float  g_C [32 * NLM];          // C[t][k]   (Legendre, inverse)
__device__ float  g_Ef[64 * 64];           // fwd DFT: [n=2m+c][p] (cos, -sin), m=0..31
__device__ float  g_Ei[63 * 128];          // inv DFT: [p][2mm+c] (cos, -sin), mm=0..62
__device__ __align__(16) float g_Z [(size_t)ZROWS * 64];  // phi-DFT outputs
__device__ float  g_fc [NR * NLM];         // gathered f at idx positions
__device__ float2 g_kqkv[NK3 * NLM];       // spectral q|k|v kernels
__device__ float2 g_koc [NKO * NLM];       // spectral output kernel [wr][k]
__device__ float2 g_kot [NLM * NKO];       // transposed [k][wr]
__device__ float2 g_G   [NR * NLM];        // FQ * conj(FK)
__device__ float2 g_FV  [NR * NLM];
__device__ float  g_W   [(size_t)65536 * 128];  // isht intermediate [(r,t)][2mm], pads 0
__device__ float  g_Asp [NR * SL];         // spatial logits -> softmax in place
__device__ float2 g_FA  [NR * NLM];
__device__ float2 g_fot [NLM * NR];

__device__ __forceinline__ int iclamp(int i, int n) {
    return (i < 0) ? 0 : ((i >= n) ? n - 1 : i);
}
__device__ __forceinline__ int isqrt_dev(int k) {
    int l = (int)sqrtf((float)k);
    while ((l + 1) * (l + 1) <= k) ++l;
    while (l * l > k) --l;
    return l;
}

// ---------------------------------------------------------------------------
// Table builder: D, C extraction + DFT twiddle matrices
// ---------------------------------------------------------------------------
__global__ void build_tables(const float* __restrict__ Ym, const float* __restrict__ Yp) {
    int i = blockIdx.x * 256 + threadIdx.x;
    if (i < 32 * NLM) {
        int t = i >> 10, k = i & 1023;
        g_D[i] = Yp[(size_t)k * SL + t * NPHI];          // Re(Ypinv[k, t*63])
        g_C[i] = Ym[(size_t)t * NPHI * NLM + k];         // Re(Ymat[t*63, k])
    }
    if (i < 64 * 64) {
        int n = i >> 6, p = i & 63;
        float v = 0.f;
        if (p < NPHI) {
            int m = n >> 1;
            int q = (m * p) % NPHI;
            float ang = 6.283185307179586f * (float)q / (float)NPHI;
            v = (n & 1) ? -sinf(ang) : cosf(ang);        // e^{-i m phi}
        }
        g_Ef[i] = v;
    }
    if (i < 63 * 128) {
        int p = i >> 7, c = i & 127;
        float v = 0.f;
        if (c < 126) {
            int mm = c >> 1, m = mm - 31;
            int q = ((m * p) % NPHI + NPHI) % NPHI;
            float ang = 6.283185307179586f * (float)q / (float)NPHI;
            v = (c & 1) ? -sinf(ang) : cosf(ang);        // Re(W e^{+im phi}) = WR cos - WI sin
        }
        g_Ei[i] = v;
    }
}

// ---------------------------------------------------------------------------
// Gather f at idx positions: [2048][1024]
// ---------------------------------------------------------------------------
__global__ void gather_fc(const float* __restrict__ f_in, int nf,
                          const int* __restrict__ idx, int ni) {
    int i = blockIdx.x * blockDim.x + threadIdx.x;
    if (i >= NR * NLM) return;
    int r = i >> 10, k = i & (NLM - 1);
    int s = idx[iclamp(k, ni)];
    s = iclamp(s, SL);
    g_fc[i] = f_in[iclamp(r * SL + s, nf)];
}

// ---------------------------------------------------------------------------
// Forward phi-DFT: Z[row][2m+c] = sum_p X[row*63+p] * Ef[2m+c][p], m=0..31
// row = (wr*32 + t); src==nullptr -> read g_Asp. Block = 64 rows.
// ---------------------------------------------------------------------------
__global__ __launch_bounds__(256) void dft_fwd(const float* __restrict__ src, int zbase) {
    __shared__ float Xs[64][65];
    __shared__ float Es[64][65];
    const int row0 = blockIdx.x * 64;
    const float* s = src ? src : g_Asp;
    for (int i = threadIdx.x; i < 64 * 63; i += 256) {
        int r = i / 63, p = i - r * 63;
        Xs[r][p] = s[(size_t)(row0 + r) * 63 + p];
    }
    for (int i = threadIdx.x; i < 64 * 64; i += 256)
        Es[i >> 6][i & 63] = g_Ef[i];
    __syncthreads();

    const int rg = threadIdx.x >> 4;          // 16 groups of 4 rows
    const int c0 = (threadIdx.x & 15) * 4;    // 4 cols
    float acc[4][4];
#pragma unroll
    for (int i = 0; i < 4; ++i)
#pragma unroll
        for (int j = 0; j < 4; ++j) acc[i][j] = 0.f;

#pragma unroll 7
    for (int p = 0; p < 63; ++p) {
        float xv[4], ev[4];
#pragma unroll
        for (int i = 0; i < 4; ++i) xv[i] = Xs[rg * 4 + i][p];
#pragma unroll
        for (int j = 0; j < 4; ++j) ev[j] = Es[c0 + j][p];
#pragma unroll
        for (int i = 0; i < 4; ++i)
#pragma unroll
            for (int j = 0; j < 4; ++j) acc[i][j] += xv[i] * ev[j];
    }
#pragma unroll
    for (int i = 0; i < 4; ++i) {
        float4 v = make_float4(acc[i][0], acc[i][1], acc[i][2], acc[i][3]);
        *reinterpret_cast<float4*>(&g_Z[(size_t)(zbase + row0 + rg * 4 + i) * 64 + c0]) = v;
    }
}

// ---------------------------------------------------------------------------
// Forward Legendre: flm[r][k] = sum_t D[t][k] * Zeff[r, m_k, t]
// Zeff for m<0 = conj(Z[|m|]) (real source). outsel: 0=kqkv, 1=koc, 2=FA
// ---------------------------------------------------------------------------
__global__ __launch_bounds__(256) void legendre_fwd(int rzbase, int outsel, int outofs) {
    const int r = blockIdx.x;
    __shared__ float Zs[32][65];
    for (int i = threadIdx.x; i < 32 * 64; i += 256)
        Zs[i >> 6][i & 63] = g_Z[(size_t)(rzbase + r) * 2048 + i];
    __syncthreads();

    float2* out = (outsel == 0) ? g_kqkv : (outsel == 1) ? g_koc : g_FA;
    for (int k = threadIdx.x; k < NLM; k += 256) {
        int l = isqrt_dev(k);
        int m = k - l * l - l;
        int am = (m < 0) ? -m : m;
        float re = 0.f, im = 0.f;
#pragma unroll 8
        for (int t = 0; t < 32; ++t) {
            float d = g_D[t * NLM + k];
            re += d * Zs[t][2 * am];
            im += d * Zs[t][2 * am + 1];
        }
        if (m < 0) im = -im;
        out[(size_t)(outofs + r) * NLM + k] = make_float2(re, im);
    }
}

// ---------------------------------------------------------------------------
// Inverse Legendre: W[(r,t)][mm] = sum_{l>=|m|} C[t][k(l,m)] * G[r][k], complex
// ---------------------------------------------------------------------------
__global__ __launch_bounds__(256) void legendre_inv() {
    const int r = blockIdx.x;
    __shared__ float2 Gs[NLM];
    for (int i = threadIdx.x; i < NLM; i += 256) Gs[i] = g_G[(size_t)r * NLM + i];
    __syncthreads();

    for (int idx = threadIdx.x; idx < 32 * 63; idx += 256) {
        int t = idx / 63, mm = idx - t * 63;
        int m = mm - 31;
        int am = (m < 0) ? -m : m;
        float re = 0.f, im = 0.f;
        for (int l = am; l < 32; ++l) {
            int k = l * l + l + m;
            float c = g_C[t * NLM + k];
            float2 g = Gs[k];
            re += c * g.x;
            im += c * g.y;
        }
        reinterpret_cast<float2*>(g_W)[(size_t)(r * 32 + t) * 64 + mm] = make_float2(re, im);
    }
}

// ---------------------------------------------------------------------------
// Inverse phi-DFT: Asp[(r,t)*63 + p] = sum_k W[(r,t)][k] * Ei[p][k], K=126(+2 pad)
// Block = 32 rows x 63 cols.
// ---------------------------------------------------------------------------
__global__ __launch_bounds__(256) void dft_inv() {
    __shared__ float Ws[32][128];
    __shared__ float Eis[63][129];
    const int row0 = blockIdx.x * 32;
    for (int i = threadIdx.x; i < 32 * 128; i += 256)
        Ws[i >> 7][i & 127] = g_W[(size_t)(row0 + (i >> 7)) * 128 + (i & 127)];
    for (int i = threadIdx.x; i < 63 * 128; i += 256)
        Eis[i >> 7][i & 127] = g_Ei[i];
    __syncthreads();

    const int rg = threadIdx.x >> 5;          // 8 groups of 4 rows
    const int c0 = (threadIdx.x & 31) * 2;    // cols c0, c0+1
    float acc[4][2];
#pragma unroll
    for (int i = 0; i < 4; ++i) { acc[i][0] = 0.f; acc[i][1] = 0.f; }

#pragma unroll 9
    for (int k = 0; k < 126; ++k) {
        float e0 = Eis[c0][k];
        float e1 = (c0 + 1 < 63) ? Eis[c0 + 1][k] : 0.f;
#pragma unroll
        for (int i = 0; i < 4; ++i) {
            float wv = Ws[rg * 4 + i][k];
            acc[i][0] += wv * e0;
            acc[i][1] += wv * e1;
        }
    }
#pragma unroll
    for (int i = 0; i < 4; ++i) {
        int row = row0 + rg * 4 + i;
        g_Asp[(size_t)row * 63 + c0] = acc[i][0];
        if (c0 + 1 < 63) g_Asp[(size_t)row * 63 + c0 + 1] = acc[i][1];
    }
}

// ---------------------------------------------------------------------------
// Complex transpose g_koc [NKO][NLM] -> g_kot [NLM][NKO]
// ---------------------------------------------------------------------------
__global__ void transpose_koc() {
    __shared__ __align__(16) float2 tile[32][33];
    int c0 = blockIdx.x * 32, r0 = blockIdx.y * 32;
#pragma unroll
    for (int j = 0; j < 4; ++j) {
        int r = r0 + threadIdx.y + j * 8;
        tile[threadIdx.y + j * 8][threadIdx.x] = g_koc[(size_t)r * NLM + c0 + threadIdx.x];
    }
    __syncthreads();
#pragma unroll
    for (int j = 0; j < 4; ++j) {
        int c = c0 + threadIdx.y + j * 8;
        g_kot[(size_t)c * NKO + r0 + threadIdx.x] = tile[threadIdx.x][threadIdx.y + j * 8];
    }
}

// ---------------------------------------------------------------------------
// Fused head-mixing: FQ/FK/FV (D=8 contraction, f real) + G = FQ * conj(FK)
// ---------------------------------------------------------------------------
__global__ __launch_bounds__(256) void qkv_g() {
    int k = blockIdx.x * 256 + threadIdx.x;
    int r = blockIdx.y;
    int b = r >> 6, ch = r & 63, h = ch >> 3, d = ch & 7;
    float qr = 0, qi = 0, kr = 0, ki = 0, vr = 0, vi = 0;
#pragma unroll
    for (int c = 0; c < 8; ++c) {
        float f = g_fc[(size_t)((b << 6) + (h << 3) + c) * NLM + k];
        int row = ((h << 3) + c) * 8 + d;
        float2 wq = g_kqkv[(size_t)row * NLM + k];
        float2 wk = g_kqkv[(size_t)(row + NKR) * NLM + k];
        float2 wv = g_kqkv[(size_t)(row + 2 * NKR) * NLM + k];
        qr += f * wq.x; qi += f * wq.y;
        kr += f * wk.x; ki += f * wk.y;
        vr += f * wv.x; vi += f * wv.y;
    }
    size_t o = (size_t)r * NLM + k;
    g_G[o]  = make_float2(qr * kr + qi * ki, qi * kr - qr * ki);
    g_FV[o] = make_float2(vr, vi);
}

// ---------------------------------------------------------------------------
// Row softmax over SL=2016 columns, in place on g_Asp
// ---------------------------------------------------------------------------
__global__ __launch_bounds__(256) void softmax_rows() {
    __shared__ float red[32];
    float* row = g_Asp + (size_t)blockIdx.x * SL;
    int tid = threadIdx.x;

    float m = -1e30f;
    for (int i = tid; i < SL; i += 256) m = fmaxf(m, row[i]);
#pragma unroll
    for (int o = 16; o; o >>= 1) m = fmaxf(m, __shfl_xor_sync(0xffffffffu, m, o));
    if ((tid & 31) == 0) red[tid >> 5] = m;
    __syncthreads();
    if (tid < 32) {
        float v = (tid < 8) ? red[tid] : -1e30f;
#pragma unroll
        for (int o = 4; o; o >>= 1) v = fmaxf(v, __shfl_xor_sync(0xffffffffu, v, o));
        if (tid == 0) red[0] = v;
    }
    __syncthreads();
    m = red[0];
    __syncthreads();

    float s = 0.f;
    for (int i = tid; i < SL; i += 256) {
        float e = expf(row[i] - m);
        row[i] = e;
        s += e;
    }
#pragma unroll
    for (int o = 16; o; o >>= 1) s += __shfl_xor_sync(0xffffffffu, s, o);
    if ((tid & 31) == 0) red[tid >> 5] = s;
    __syncthreads();
    if (tid < 32) {
        float v = (tid < 8) ? red[tid] : 0.f;
#pragma unroll
        for (int o = 4; o; o >>= 1) v += __shfl_xor_sync(0xffffffffu, v, o);
        if (tid == 0) red[0] = v;
    }
    __syncthreads();
    float inv = 1.0f / red[0];
    for (int i = tid; i < SL; i += 256) row[i] *= inv;
}

// ---------------------------------------------------------------------------
// f_out = FV * FA (complex), transposed into [k][r] layout
// ---------------------------------------------------------------------------
__global__ void fout_transpose() {
    __shared__ __align__(16) float2 tile[32][33];
    int k0 = blockIdx.x * 32, r0 = blockIdx.y * 32;
#pragma unroll
    for (int j = 0; j < 4; ++j) {
        int r = r0 + threadIdx.y + j * 8;
        size_t p = (size_t)r * NLM + k0 + threadIdx.x;
        float2 v = g_FV[p];
        float2 a = g_FA[p];
        tile[threadIdx.y + j * 8][threadIdx.x] =
            make_float2(v.x * a.x - v.y * a.y, v.x * a.y + v.y * a.x);
    }
    __syncthreads();
#pragma unroll
    for (int j = 0; j < 4; ++j) {
        int k = k0 + threadIdx.y + j * 8;
        g_fot[(size_t)k * NR + r0 + threadIdx.x] = tile[threadIdx.x][threadIdx.y + j * 8];
    }
}

// ---------------------------------------------------------------------------
// Output: per-k batched complex GEMM [32b,64c]x[64o,64c]^T, REAL part scatter
// ---------------------------------------------------------------------------
__global__ void zero_out_f(float* out, int n) {
    int i = blockIdx.x * blockDim.x + threadIdx.x;
    if (i < n) out[i] = 0.f;
}

__global__ __launch_bounds__(256) void out_scatter(const int* __restrict__ idx, int ni,
                                                   float* __restrict__ out) {
    __shared__ __align__(16) float2 Fsh[64 * 33];   // [c][b] padded
    int k = blockIdx.x;
    for (int j = threadIdx.x; j < NR; j += 256) {
        float2 v = g_fot[(size_t)k * NR + j];
        int bb = j >> 6, cc = j & 63;
        Fsh[cc * 33 + bb] = v;
    }
    __syncthreads();
    int w = threadIdx.x >> 5;
    int b = threadIdx.x & 31;
    const float2* W = g_kot + (size_t)k * NKO;
    float re[8];
#pragma unroll
    for (int i = 0; i < 8; ++i) re[i] = 0.f;
#pragma unroll 4
    for (int c = 0; c < 64; ++c) {
        float2 F = Fsh[c * 33 + b];
#pragma unroll
        for (int i = 0; i < 8; ++i) {
            float2 ww = W[(w + i * 8) * 64 + c];
            re[i] += F.x * ww.x - F.y * ww.y;   // real part only needed
        }
    }
    int s = idx[iclamp(k, ni)];
    s = iclamp(s, SL);
#pragma unroll
    for (int i = 0; i < 8; ++i) {
        int o = w + i * 8;
        out[(size_t)((b << 6) + o) * SL + s] = re[i];
    }
}

// ---------------------------------------------------------------------------
// Launch
// ---------------------------------------------------------------------------
extern "C" void kernel_launch(void* const* d_in, const int* in_sizes, int n_in,
                              void* d_out, int out_size) {
    const float* f_in = (const float*)d_in[0];
    const float* kq   = (const float*)d_in[1];
    const float* kk   = (const float*)d_in[2];
    const float* kv   = (const float*)d_in[3];
    const float* ko   = (const float*)d_in[4];
    const float* Ym   = (const float*)d_in[5];
    const float* Yp   = (const float*)d_in[6];
    const int*   idx  = (const int*)d_in[7];
    float* out = (float*)d_out;

    // tables + gather
    build_tables<<<128, 256>>>(Ym, Yp);
    gather_fc<<<(NR * NLM) / 256, 256>>>(f_in, in_sizes[0], idx, in_sizes[7]);

    // forward SHT of weights: phi-DFT (reads inputs in place) + Legendre
    dft_fwd<<<256,  256>>>(kq, 0);        // Z rows [0, 16384)
    dft_fwd<<<256,  256>>>(kk, 16384);    // [16384, 32768)
    dft_fwd<<<256,  256>>>(kv, 32768);    // [32768, 49152)
    dft_fwd<<<2048, 256>>>(ko, 49152);    // [49152, 180224)
    legendre_fwd<<<1536, 256>>>(0, 0, 0);       // -> g_kqkv
    legendre_fwd<<<4096, 256>>>(1536, 1, 0);    // -> g_koc
    transpose_koc<<<dim3(NLM / 32, NKO / 32), dim3(32, 8)>>>();

    // head mixing + G = FQ * conj(FK)
    qkv_g<<<dim3(NLM / 256, NR), 256>>>();

    // inverse SHT of G -> spatial logits
    legendre_inv<<<NR, 256>>>();
    dft_inv<<<NR, 256>>>();               // 65536 rows / 32 = 2048 blocks

    softmax_rows<<<NR, 256>>>();

    // forward SHT of softmax(A) -> FA
    dft_fwd<<<1024, 256>>>(nullptr, 180224);    // Z rows [180224, 245760)
    legendre_fwd<<<2048, 256>>>(5632, 2, 0);    // -> g_FA

    // f_out = FV * FA -> [k][r]; final projection + scatter (real part)
    fout_transpose<<<dim3(NLM / 32, NR / 32), dim3(32, 8)>>>();
    zero_out_f<<<(NOUT + 255) / 256, 256>>>(out, NOUT);
    out_scatter<<<NLM, 256>>>(idx, in_sizes[7], out);
}

// round 9
// speedup vs baseline: 5.1697x; 1.1094x over previous
#include <cuda_runtime.h>
#include <math.h>

// ---------------------------------------------------------------------------
// L=32, M=63, SL=2016, nlm=1024, B=32, C=64, H=8, D=8
// Separable SHT (validated R7/R8, rel_err 7e-7):
//   Ypinv[k, t*63+p] = D[k,t] e^{-i m_k phi_p},  D = Re(Ypinv) at p=0
//   Ymat [t*63+p, k] = C[t,k] e^{+i m_k phi_p},  C = Re(Ymat)  at p=0
// All per-row work (qkv -> isht -> softmax -> fsht -> FV*FA) fused in one
// kernel; weight transforms fused in another. Complex I/O = real part only.
// ---------------------------------------------------------------------------
#define SL    2016
#define NPHI  63
#define NLM   1024
#define NR    2048
#define NKR   512
#define NK3   1536
#define NKO   4096
#define NOUT  (32 * 64 * SL)

__device__ float  g_D [32 * NLM];      // forward Legendre D[t][k]
__device__ float  g_C [32 * NLM];      // inverse Legendre C[t][k]
__device__ float  g_Ef[64 * 64];       // twiddles [n=2m+c][p]: cos(m phi_p), -sin(m phi_p); p=63 col = 0
__device__ float  g_fc [NR * NLM];     // gathered f at idx positions
__device__ float2 g_kqkv[NK3 * NLM];   // spectral q|k|v kernels [row][k]
__device__ float2 g_koc [NKO * NLM];   // spectral output kernel [row][k]
__device__ float2 g_kot [NLM * NKO];   // transposed [k][row]
__device__ float2 g_P   [NR * NLM];    // FV * FA  [r][k]
__device__ float2 g_fot [NLM * NR];    // transposed [k][r]

__device__ __forceinline__ int iclamp(int i, int n) {
    return (i < 0) ? 0 : ((i >= n) ? n - 1 : i);
}
__device__ __forceinline__ int isqrt_dev(int k) {
    int l = (int)sqrtf((float)k);
    while ((l + 1) * (l + 1) <= k) ++l;
    while (l * l > k) --l;
    return l;
}

// ---------------------------------------------------------------------------
// Tables: D, C extraction + twiddle matrix (shared by fwd and folded-inverse)
// ---------------------------------------------------------------------------
__global__ void build_tables(const float* __restrict__ Ym, const float* __restrict__ Yp) {
    int i = blockIdx.x * 256 + threadIdx.x;
    if (i < 32 * NLM) {
        int t = i >> 10, k = i & 1023;
        g_D[i] = Yp[(size_t)k * SL + t * NPHI];
        g_C[i] = Ym[(size_t)t * NPHI * NLM + k];
    }
    if (i < 64 * 64) {
        int n = i >> 6, p = i & 63;
        float v = 0.f;
        if (p < NPHI) {
            int m = n >> 1;
            int q = (m * p) % NPHI;
            float ang = 6.283185307179586f * (float)q / (float)NPHI;
            v = (n & 1) ? -sinf(ang) : cosf(ang);
        }
        g_Ef[i] = v;
    }
}

__global__ void gather_fc(const float* __restrict__ f_in, int nf,
                          const int* __restrict__ idx, int ni) {
    int i = blockIdx.x * blockDim.x + threadIdx.x;
    if (i >= NR * NLM) return;
    int r = i >> 10, k = i & (NLM - 1);
    int s = idx[iclamp(k, ni)];
    s = iclamp(s, SL);
    g_fc[i] = f_in[iclamp(r * SL + s, nf)];
}

// ---------------------------------------------------------------------------
// Fused forward SHT of weights: one block per weight row (5632 rows).
// phi-DFT (32x64 from 32x63) + Legendre -> spectral row.
// ---------------------------------------------------------------------------
__global__ __launch_bounds__(128) void wfwd(const float* __restrict__ kq,
                                            const float* __restrict__ kk,
                                            const float* __restrict__ kv,
                                            const float* __restrict__ ko) {
    int r = blockIdx.x;
    const float* src; int row; float2* out; int outr;
    if (r < 512)       { src = kq; row = r;        out = g_kqkv; outr = r; }
    else if (r < 1024) { src = kk; row = r - 512;  out = g_kqkv; outr = r; }
    else if (r < 1536) { src = kv; row = r - 1024; out = g_kqkv; outr = r; }
    else               { src = ko; row = r - 1536; out = g_koc;  outr = r - 1536; }

    __shared__ float Ef[64][65];
    __shared__ float X [32][64];
    __shared__ float Z [32][65];
    const int tid = threadIdx.x;

    for (int i = tid; i < 64 * 64; i += 128) Ef[i >> 6][i & 63] = g_Ef[i];
    for (int i = tid; i < 32 * 63; i += 128) {
        int t = i / 63, p = i - t * 63;
        X[t][p] = src[(size_t)row * SL + i];
    }
    __syncthreads();

    // Z[t][c] = sum_p X[t][p] * Ef[c][p]   (4x4 tiles, 8x16 groups)
    {
        const int tg = tid >> 4, cg = tid & 15;
        float acc[4][4];
#pragma unroll
        for (int i = 0; i < 4; ++i)
#pragma unroll
            for (int j = 0; j < 4; ++j) acc[i][j] = 0.f;
#pragma unroll 7
        for (int p = 0; p < 63; ++p) {
            float xv[4], ev[4];
#pragma unroll
            for (int i = 0; i < 4; ++i) xv[i] = X[tg * 4 + i][p];
#pragma unroll
            for (int j = 0; j < 4; ++j) ev[j] = Ef[cg * 4 + j][p];
#pragma unroll
            for (int i = 0; i < 4; ++i)
#pragma unroll
                for (int j = 0; j < 4; ++j) acc[i][j] += xv[i] * ev[j];
        }
#pragma unroll
        for (int i = 0; i < 4; ++i)
#pragma unroll
            for (int j = 0; j < 4; ++j) Z[tg * 4 + i][cg * 4 + j] = acc[i][j];
    }
    __syncthreads();

    // Legendre: out[k] = sum_t D[t][k] * Z[t][2am(,+1)]; im flip for m<0
    for (int k = tid; k < NLM; k += 128) {
        int l = isqrt_dev(k);
        int m = k - l * l - l;
        int am = (m < 0) ? -m : m;
        float re = 0.f, im = 0.f;
#pragma unroll 8
        for (int t = 0; t < 32; ++t) {
            float dd = g_D[t * NLM + k];
            re += dd * Z[t][2 * am];
            im += dd * Z[t][2 * am + 1];
        }
        if (m < 0) im = -im;
        out[(size_t)outr * NLM + k] = make_float2(re, im);
    }
}

// ---------------------------------------------------------------------------
// MEGA: per attention-row r (2048 blocks):
//  qkv mix -> G (smem), FV (regs) -> folded inverse Legendre (u) ->
//  inverse phi-DFT -> softmax -> forward phi-DFT -> forward Legendre -> FV*FA
// ---------------------------------------------------------------------------
__global__ __launch_bounds__(256) void mega() {
    const int r = blockIdx.x;
    const int b = r >> 6, ch = r & 63, h = ch >> 3, d = ch & 7;

    __shared__ float  Ef[64][65];
    __shared__ float2 Gb[1024];        // G, later reused as A[32][64] floats
    __shared__ float  U [32][65];      // u (folded W), later reused as Z
    __shared__ float  red[32];
    const int tid = threadIdx.x;

    for (int i = tid; i < 64 * 64; i += 256) Ef[i >> 6][i & 63] = g_Ef[i];

    // ---- qkv head mixing: G = FQ conj(FK) to smem, FV to registers --------
    float2 fv[4];
#pragma unroll
    for (int i = 0; i < 4; ++i) {
        int k = tid + i * 256;
        float qr = 0, qi = 0, kr = 0, ki = 0, vr = 0, vi = 0;
#pragma unroll
        for (int c = 0; c < 8; ++c) {
            float f = g_fc[(size_t)((b << 6) + (h << 3) + c) * NLM + k];
            int row = ((h << 3) + c) * 8 + d;
            float2 wq = g_kqkv[(size_t)row * NLM + k];
            float2 wk = g_kqkv[(size_t)(row + NKR) * NLM + k];
            float2 wv = g_kqkv[(size_t)(row + 2 * NKR) * NLM + k];
            qr += f * wq.x; qi += f * wq.y;
            kr += f * wk.x; ki += f * wk.y;
            vr += f * wv.x; vi += f * wv.y;
        }
        Gb[k] = make_float2(qr * kr + qi * ki, qi * kr - qr * ki);
        fv[i] = make_float2(vr, vi);
    }
    __syncthreads();

    // ---- folded inverse Legendre: u[t][2m]=WR[m]+WR[-m], u[t][2m+1]=WI[m]-WI[-m]
    for (int it = tid; it < 1024; it += 256) {
        int t = it >> 5, m = it & 31;
        float ur, ui;
        if (m == 0) {
            float re = 0.f;
            for (int l = 0; l < 32; ++l) {
                int k = l * l + l;
                re += g_C[t * NLM + k] * Gb[k].x;
            }
            ur = re; ui = 0.f;
        } else {
            float rp = 0.f, ip = 0.f, rm = 0.f, im2 = 0.f;
            for (int l = m; l < 32; ++l) {
                int kb = l * l + l;
                float cp = g_C[t * NLM + kb + m];
                float cm = g_C[t * NLM + kb - m];
                float2 gp = Gb[kb + m];
                float2 gm = Gb[kb - m];
                rp += cp * gp.x; ip += cp * gp.y;
                rm += cm * gm.x; im2 += cm * gm.y;
            }
            ur = rp + rm; ui = ip - im2;
        }
        U[t][2 * m]     = ur;
        U[t][2 * m + 1] = ui;
    }
    __syncthreads();

    // ---- inverse phi-DFT: A[t][p] = sum_c u[t][c] * Ef[c][p]  (2x4 tiles)
    float* A = reinterpret_cast<float*>(Gb);   // 2048 floats [t*64+p]
    {
        const int tg = tid >> 4, pg = tid & 15;   // t0=2tg, p0=4pg
        float acc[2][4];
#pragma unroll
        for (int i = 0; i < 2; ++i)
#pragma unroll
            for (int j = 0; j < 4; ++j) acc[i][j] = 0.f;
#pragma unroll 8
        for (int c = 0; c < 64; ++c) {
            float u0 = U[tg * 2][c], u1 = U[tg * 2 + 1][c];
            float ev[4];
#pragma unroll
            for (int j = 0; j < 4; ++j) ev[j] = Ef[c][pg * 4 + j];
#pragma unroll
            for (int j = 0; j < 4; ++j) {
                acc[0][j] += u0 * ev[j];
                acc[1][j] += u1 * ev[j];
            }
        }
#pragma unroll
        for (int i = 0; i < 2; ++i)
#pragma unroll
            for (int j = 0; j < 4; ++j) A[(tg * 2 + i) * 64 + pg * 4 + j] = acc[i][j];
    }
    __syncthreads();
    if (tid < 32) A[tid * 64 + 63] = -1e30f;    // pad col out of softmax
    __syncthreads();

    // ---- softmax over 2016 real values (pad col contributes exp->0) -------
    {
        float m = -1e30f;
        for (int i = tid; i < 2048; i += 256) m = fmaxf(m, A[i]);
#pragma unroll
        for (int o = 16; o; o >>= 1) m = fmaxf(m, __shfl_xor_sync(0xffffffffu, m, o));
        if ((tid & 31) == 0) red[tid >> 5] = m;
        __syncthreads();
        if (tid < 32) {
            float v = (tid < 8) ? red[tid] : -1e30f;
#pragma unroll
            for (int o = 4; o; o >>= 1) v = fmaxf(v, __shfl_xor_sync(0xffffffffu, v, o));
            if (tid == 0) red[0] = v;
        }
        __syncthreads();
        m = red[0];
        __syncthreads();
        float s = 0.f;
        for (int i = tid; i < 2048; i += 256) {
            float e = expf(A[i] - m);
            A[i] = e;
            s += e;
        }
#pragma unroll
        for (int o = 16; o; o >>= 1) s += __shfl_xor_sync(0xffffffffu, s, o);
        if ((tid & 31) == 0) red[tid >> 5] = s;
        __syncthreads();
        if (tid < 32) {
            float v = (tid < 8) ? red[tid] : 0.f;
#pragma unroll
            for (int o = 4; o; o >>= 1) v += __shfl_xor_sync(0xffffffffu, v, o);
            if (tid == 0) red[0] = v;
        }
        __syncthreads();
        float inv = 1.0f / red[0];
        for (int i = tid; i < 2048; i += 256) A[i] *= inv;
    }
    __syncthreads();

    // ---- forward phi-DFT: Z[t][c] = sum_p A[t][p] * Ef[c][p] (reuses U) ---
    {
        const int tg = tid >> 4, cg = tid & 15;   // t0=2tg, c0=4cg
        float acc[2][4];
#pragma unroll
        for (int i = 0; i < 2; ++i)
#pragma unroll
            for (int j = 0; j < 4; ++j) acc[i][j] = 0.f;
#pragma unroll 7
        for (int p = 0; p < 63; ++p) {
            float a0 = A[(tg * 2) * 64 + p], a1 = A[(tg * 2 + 1) * 64 + p];
            float ev[4];
#pragma unroll
            for (int j = 0; j < 4; ++j) ev[j] = Ef[cg * 4 + j][p];
#pragma unroll
            for (int j = 0; j < 4; ++j) {
                acc[0][j] += a0 * ev[j];
                acc[1][j] += a1 * ev[j];
            }
        }
#pragma unroll
        for (int i = 0; i < 2; ++i)
#pragma unroll
            for (int j = 0; j < 4; ++j) U[tg * 2 + i][cg * 4 + j] = acc[i][j];
    }
    __syncthreads();

    // ---- forward Legendre + FV*FA product ---------------------------------
#pragma unroll
    for (int i = 0; i < 4; ++i) {
        int k = tid + i * 256;
        int l = isqrt_dev(k);
        int m = k - l * l - l;
        int am = (m < 0) ? -m : m;
        float re = 0.f, im = 0.f;
#pragma unroll 8
        for (int t = 0; t < 32; ++t) {
            float dd = g_D[t * NLM + k];
            re += dd * U[t][2 * am];
            im += dd * U[t][2 * am + 1];
        }
        if (m < 0) im = -im;
        g_P[(size_t)r * NLM + k] =
            make_float2(fv[i].x * re - fv[i].y * im, fv[i].x * im + fv[i].y * re);
    }
}

// ---------------------------------------------------------------------------
// Complex transpose: sel=0: g_koc[4096][1024]->g_kot; sel=1: g_P[2048][1024]->g_fot
// ---------------------------------------------------------------------------
__global__ void transpose_gen(int sel) {
    const float2* in = sel ? g_P : g_koc;
    float2* out = sel ? g_fot : g_kot;
    const int R = sel ? NR : NKO;
    __shared__ __align__(16) float2 tile[32][33];
    int c0 = blockIdx.x * 32, r0 = blockIdx.y * 32;
#pragma unroll
    for (int j = 0; j < 4; ++j) {
        int r = r0 + threadIdx.y + j * 8;
        tile[threadIdx.y + j * 8][threadIdx.x] = in[(size_t)r * NLM + c0 + threadIdx.x];
    }
    __syncthreads();
#pragma unroll
    for (int j = 0; j < 4; ++j) {
        int c = c0 + threadIdx.y + j * 8;
        out[(size_t)c * R + r0 + threadIdx.x] = tile[threadIdx.x][threadIdx.y + j * 8];
    }
}

// ---------------------------------------------------------------------------
// Output: zero + per-k batched complex GEMM [32b,64c]x[64o,64c]^T, real scatter
// ---------------------------------------------------------------------------
__global__ void zero_out_f(float* out, int n) {
    int i = blockIdx.x * blockDim.x + threadIdx.x;
    if (i < n) out[i] = 0.f;
}

__global__ __launch_bounds__(256) void out_scatter(const int* __restrict__ idx, int ni,
                                                   float* __restrict__ out) {
    __shared__ __align__(16) float2 Fsh[64 * 33];
    int k = blockIdx.x;
    for (int j = threadIdx.x; j < NR; j += 256) {
        float2 v = g_fot[(size_t)k * NR + j];
        int bb = j >> 6, cc = j & 63;
        Fsh[cc * 33 + bb] = v;
    }
    __syncthreads();
    int w = threadIdx.x >> 5;
    int b = threadIdx.x & 31;
    const float2* W = g_kot + (size_t)k * NKO;
    float re[8];
#pragma unroll
    for (int i = 0; i < 8; ++i) re[i] = 0.f;
#pragma unroll 4
    for (int c = 0; c < 64; ++c) {
        float2 F = Fsh[c * 33 + b];
#pragma unroll
        for (int i = 0; i < 8; ++i) {
            float2 ww = W[(w + i * 8) * 64 + c];
            re[i] += F.x * ww.x - F.y * ww.y;
        }
    }
    int s = idx[iclamp(k, ni)];
    s = iclamp(s, SL);
#pragma unroll
    for (int i = 0; i < 8; ++i) {
        int o = w + i * 8;
        out[(size_t)((b << 6) + o) * SL + s] = re[i];
    }
}

// ---------------------------------------------------------------------------
// Launch
// ---------------------------------------------------------------------------
extern "C" void kernel_launch(void* const* d_in, const int* in_sizes, int n_in,
                              void* d_out, int out_size) {
    const float* f_in = (const float*)d_in[0];
    const float* kq   = (const float*)d_in[1];
    const float* kk   = (const float*)d_in[2];
    const float* kv   = (const float*)d_in[3];
    const float* ko   = (const float*)d_in[4];
    const float* Ym   = (const float*)d_in[5];
    const float* Yp   = (const float*)d_in[6];
    const int*   idx  = (const int*)d_in[7];
    float* out = (float*)d_out;

    build_tables<<<128, 256>>>(Ym, Yp);
    gather_fc<<<(NR * NLM) / 256, 256>>>(f_in, in_sizes[0], idx, in_sizes[7]);

    // fused forward SHT of all weights (5632 rows)
    wfwd<<<5632, 128>>>(kq, kk, kv, ko);
    transpose_gen<<<dim3(32, 128), dim3(32, 8)>>>(0);   // koc -> kot

    // fused per-row attention chain
    mega<<<NR, 256>>>();
    transpose_gen<<<dim3(32, 64), dim3(32, 8)>>>(1);    // P -> fot

    zero_out_f<<<(NOUT + 255) / 256, 256>>>(out, NOUT);
    out_scatter<<<NLM, 256>>>(idx, in_sizes[7], out);
}